// round 14
// baseline (speedup 1.0000x reference)
#include <cuda_runtime.h>
#include <cstdint>

typedef unsigned long long u64;
typedef unsigned int u32;

#define NROWS 1024
#define NCOLS 16384
#define NTOT (NROWS*NCOLS)
#define CAP 32768
#define FBINS 4096
#define HLO 2.0f
#define HSCALE 1024.0f
#define BIN_MIN 1060      // value threshold ~= 3.035
#define BCAP 128

#define SC_GRID 4096
#define SC_BLK 256
#define SC_STRIDE (SC_GRID*SC_BLK)   // NTOT/4 = 4*SC_STRIDE exactly

#define STAGE_KEYS 10240
#define PHA_KEYS 2048
#define PHA_WINS (PHA_KEYS/32)          // 64
#define COMP_CHUNKS ((STAGE_KEYS-PHA_KEYS)/1024)  // 8
#define MAXB_WINS ((STAGE_KEYS-PHA_KEYS+31)/32)   // 256
#define FLAT_INVALID 0xFFFFFFFFu

#define SB_WARPS 8

// device-global scratch (no allocations allowed)
// Self-cleaning invariant: at kernel_launch entry, g_bincnt[]==0 and
// g_total==g_overflow==0 (zero-init at load; re-established every call).
__device__ u32 g_bincnt[FBINS];
__device__ u32 g_binoff[FBINS];
__device__ u32 g_total;
__device__ u32 g_overflow;
__device__ u64 g_bucket[FBINS * BCAP];   // 4 MB
__device__ u64 g_keys[CAP];

__device__ __forceinline__ int binof(float v) {
    int b = (int)((v - HLO) * HSCALE);
    return (b > FBINS - 1) ? (FBINS - 1) : b;
}

// ONE full-matrix pass: scatter candidates (binof(v) >= BIN_MIN) into buckets
__global__ void __launch_bounds__(SC_BLK)
k_scatter(const float4* __restrict__ c4) {
    int idx = blockIdx.x * SC_BLK + threadIdx.x;
    float4 vv[4];
    #pragma unroll
    for (int k = 0; k < 4; k++) vv[k] = c4[idx + k * SC_STRIDE];   // MLP=4
    #pragma unroll
    for (int k = 0; k < 4; k++) {
        int i = idx + k * SC_STRIDE;
        float a[4] = { vv[k].x, vv[k].y, vv[k].z, vv[k].w };
        #pragma unroll
        for (int q = 0; q < 4; q++) {
            if (a[q] >= 3.0f) {
                int b = binof(a[q]);
                if (b >= BIN_MIN) {
                    u32 pos = atomicAdd(&g_bincnt[b], 1u);
                    if (pos < BCAP) {
                        u32 flat = (u32)(i * 4 + q);
                        u32 enc = __float_as_uint(a[q]);  // candidates > 0: bits order-preserving
                        g_bucket[b * BCAP + pos] = ((u64)enc << 24) | (u64)(0xFFFFFFu - flat);
                    } else {
                        g_overflow = 1;
                    }
                }
            }
        }
    }
}

// one block: suffix-sum bucket counts (descending bins) via shuffle scan
__global__ void __launch_bounds__(1024)
k_scan() {
    __shared__ u32 warpsum[32];
    int tid = threadIdx.x;
    int lane = tid & 31, w = tid >> 5;

    u32 x[4], pre[4];
    u32 run = 0;
    #pragma unroll
    for (int q = 0; q < 4; q++) {
        int b = FBINS - 1 - (tid * 4 + q);
        x[q] = g_bincnt[b];
        pre[q] = run;
        run += x[q];
    }
    u32 v = run;
    #pragma unroll
    for (int o = 1; o < 32; o <<= 1) {
        u32 t = __shfl_up_sync(0xFFFFFFFFu, v, o);
        if (lane >= o) v += t;
    }
    if (lane == 31) warpsum[w] = v;
    __syncthreads();
    if (w == 0) {
        u32 s = warpsum[lane];
        #pragma unroll
        for (int o = 1; o < 32; o <<= 1) {
            u32 t = __shfl_up_sync(0xFFFFFFFFu, s, o);
            if (lane >= o) s += t;
        }
        warpsum[lane] = s;
    }
    __syncthreads();
    u32 excl = v - run + ((w > 0) ? warpsum[w - 1] : 0u);

    #pragma unroll
    for (int q = 0; q < 4; q++) {
        int b = FBINS - 1 - (tid * 4 + q);
        u32 S = excl + pre[q] + x[q];
        g_binoff[b] = S - x[q];
    }
    if (tid == 0) {
        u32 total = warpsum[31];
        if (total > CAP) { g_overflow = 1; total = 0; }
        g_total = total;
    }
}

// warp-per-bin: sort bucket desc (<=128 elems) into g_keys; self-clean bincnt
__global__ void __launch_bounds__(SB_WARPS * 32)
k_sortbins() {
    __shared__ u64 sk[SB_WARPS][BCAP];
    int w = threadIdx.x >> 5, lane = threadIdx.x & 31;
    int b = blockIdx.x * SB_WARPS + w;
    u32 cnt = g_bincnt[b];
    if (lane == 0) g_bincnt[b] = 0;          // self-clean for next call
    if (cnt == 0) return;
    if (cnt > BCAP) cnt = BCAP;              // overflow already flagged; data unused
    u32 off = g_binoff[b];
    if (cnt == 1) { if (lane == 0) g_keys[off] = g_bucket[b * BCAP]; return; }

    u32 m = 2; while (m < cnt) m <<= 1;      // m <= 128
    for (u32 i = lane; i < m; i += 32) sk[w][i] = (i < cnt) ? g_bucket[b * BCAP + i] : 0ull;
    __syncwarp();
    for (u32 k = 2; k <= m; k <<= 1) {
        for (u32 j = k >> 1; j > 0; j >>= 1) {
            for (u32 i = lane; i < m; i += 32) {
                u32 p = i ^ j;
                if (p > i) {
                    u64 a = sk[w][i], bb = sk[w][p];
                    bool desc = ((i & k) == 0);
                    if (desc ? (a < bb) : (a > bb)) { sk[w][i] = bb; sk[w][p] = a; }
                }
            }
            __syncwarp();
        }
    }
    for (u32 i = lane; i < cnt; i += 32) g_keys[off + i] = sk[w][i];
}

__device__ __forceinline__ bool bit_test(const u32* bits, int i) {
    return (bits[i >> 5] >> (i & 31)) & 1u;
}

// Scan one staged region (warp 0 only). Register-only quest resolution:
// acc starts as valid & ~conf (no earlier in-window row/col match at all ->
// exactly greedy-accepted). Each quest lane q (valid but window-conflicted)
// is accepted iff no in-window ACCEPTED earlier lane shares its row/col:
// (myConfMask_q & acc) == 0, resolved in lane order -> acc = exact
// sequential-greedy-within-window fixpoint (accepted set pairwise disjoint).
__device__ __forceinline__ int scan_staged(
    const u32* sFlat, int nkeys, const u32* sConf, int lane,
    unsigned char* rowUsedB, u32* colUsed, unsigned short* colOf, int assigned)
{
    int nw = (nkeys + 31) >> 5;
    u32 flat = (lane < nkeys) ? sFlat[lane] : FLAT_INVALID;
    for (int w = 0; w < nw && assigned < NROWS; w++) {
        int ni = (w + 1) * 32 + lane;
        u32 nflat = (ni < nkeys) ? sFlat[ni] : FLAT_INVALID;
        u32 conf = sConf[w];
        int r = (int)((flat >> 14) & 1023u);
        int c = (int)(flat & 0x3FFFu);
        bool valid = (flat != FLAT_INVALID) && !rowUsedB[r]
                     && !((colUsed[c >> 5] >> (c & 31)) & 1u);
        u32 vm = __ballot_sync(0xFFFFFFFFu, valid);
        u32 acc = vm & ~conf;
        u32 quest = vm & conf;
        if (quest) {
            u32 rkey = (flat != FLAT_INVALID) ? (u32)r : (u32)(NROWS + lane);
            u32 ckey = (flat != FLAT_INVALID) ? (u32)c : (u32)(NCOLS + lane);
            u32 mR = __match_any_sync(0xFFFFFFFFu, rkey);
            u32 mC = __match_any_sync(0xFFFFFFFFu, ckey);
            u32 myConf = (mR | mC) & ((1u << lane) - 1u);
            while (quest) {
                int q = __ffs(quest) - 1; quest &= quest - 1u;
                u32 em = __shfl_sync(0xFFFFFFFFu, myConf, q);
                if ((em & acc) == 0u) acc |= (1u << q);
            }
        }
        if ((acc >> lane) & 1u) {
            rowUsedB[r] = 1;                              // distinct rows: plain store
            atomicOr(&colUsed[c >> 5], 1u << (c & 31));   // distinct cols, shared words
            colOf[r] = (unsigned short)c;
        }
        assigned += __popc(acc);
        __syncwarp();
        flat = nflat;
    }
    return assigned;
}

// greedy scan over globally-descending keys + exact fallback + output
__global__ void __launch_bounds__(1024, 1)
k_final(const float* __restrict__ cost, float* __restrict__ out, int out_size) {
    __shared__ u32 sFlat[STAGE_KEYS];          // 40960 B
    __shared__ u32 sConfA[PHA_WINS];           // 256 B
    __shared__ u32 sConfB[MAXB_WINS];          // 1024 B
    __shared__ unsigned char rowUsedB[NROWS];  // 1024 B
    __shared__ u32 colUsed[NCOLS / 32];        // 2048 B
    __shared__ unsigned short colOf[NROWS];    // 2048 B
    __shared__ u32 warpS[32];
    __shared__ u64 redBuf[32];
    __shared__ int scnt_s, m2_s;

    int tid = threadIdx.x;
    int lane = tid & 31;
    int wid = tid >> 5;
    u32 total = g_total;
    if (g_overflow) total = 0;   // pathological: pure-fallback path (exact)

    for (int i = tid; i < NCOLS / 32; i += 1024) colUsed[i] = 0;
    for (int i = tid; i < NROWS; i += 1024) { rowUsedB[i] = 0; colOf[i] = 0; }
    if (tid == 0) { scnt_s = 0; m2_s = 0; }

    // ---- stage first STAGE_KEYS flats into shared (all warps) ----
    for (int i = tid; i < STAGE_KEYS; i += 1024)
        sFlat[i] = (i < (int)total) ? (0xFFFFFFu - (u32)(g_keys[i] & 0xFFFFFFu))
                                    : FLAT_INVALID;
    __syncthreads();

    // ---- precompute phase-A conflict masks (warps in parallel; 2 per warp) ----
    for (int w = wid; w < PHA_WINS; w += 32) {
        u32 flat = sFlat[w * 32 + lane];
        bool v = (flat != FLAT_INVALID);
        u32 rkey = v ? ((flat >> 14) & 1023u) : (u32)(NROWS + lane);
        u32 ckey = v ? (flat & 0x3FFFu) : (u32)(NCOLS + lane);
        u32 mR = __match_any_sync(0xFFFFFFFFu, rkey);
        u32 mC = __match_any_sync(0xFFFFFFFFu, ckey);
        u32 earlier = (1u << lane) - 1u;
        bool conf = (((mR | mC) & earlier) != 0u);
        u32 cm = __ballot_sync(0xFFFFFFFFu, conf);
        if (lane == 0) sConfA[w] = cm;
    }
    __syncthreads();

    // ================= PHASE A: warp 0, first PHA_KEYS keys =================
    if (wid == 0) {
        int lim = ((int)total < PHA_KEYS) ? (int)total : PHA_KEYS;
        int a2 = scan_staged(sFlat, lim, sConfA, lane, rowUsedB, colUsed, colOf, 0);
        if (lane == 0) scnt_s = a2;
    }
    __syncthreads();

    // ====== MID-SCAN COMPACTION (all threads): keep keys in [PHA_KEYS,
    // STAGE_KEYS) whose row AND col are still free; order-preserving.
    // Dropping row/col-dead keys is greedy-neutral; writes land in
    // sFlat[0 .. m2) which never overlaps the not-yet-read region. ======
    {
        int m2base = 0;
        for (int k = 0; k < COMP_CHUNKS; k++) {
            int idx = PHA_KEYS + k * 1024 + tid;
            u32 f = sFlat[idx];
            bool keep = (f != FLAT_INVALID) && !rowUsedB[(f >> 14) & 1023u]
                        && !bit_test(colUsed, f & 0x3FFF);
            u32 ball = __ballot_sync(0xFFFFFFFFu, keep);
            int myoff = __popc(ball & ((1u << lane) - 1u));
            if (lane == 0) warpS[wid] = (u32)__popc(ball);
            __syncthreads();
            if (tid < 32) {
                u32 v = warpS[tid];
                #pragma unroll
                for (int o = 1; o < 32; o <<= 1) {
                    u32 t2 = __shfl_up_sync(0xFFFFFFFFu, v, o);
                    if (tid >= o) v += t2;
                }
                warpS[tid] = v;
            }
            __syncthreads();
            int wexcl = (wid > 0) ? (int)warpS[wid - 1] : 0;
            int chunkTot = (int)warpS[31];
            if (keep) sFlat[m2base + wexcl + myoff] = f;
            m2base += chunkTot;
            __syncthreads();
        }
        if (tid == 0) m2_s = m2base;
    }
    __syncthreads();

    // ---- precompute phase-B conflict masks over compacted list ----
    int m2 = m2_s;
    int nwinB = (m2 + 31) >> 5;
    for (int w = wid; w < nwinB; w += 32) {
        int i = w * 32 + lane;
        u32 flat = (i < m2) ? sFlat[i] : FLAT_INVALID;
        bool v = (flat != FLAT_INVALID);
        u32 rkey = v ? ((flat >> 14) & 1023u) : (u32)(NROWS + lane);
        u32 ckey = v ? (flat & 0x3FFFu) : (u32)(NCOLS + lane);
        u32 mR = __match_any_sync(0xFFFFFFFFu, rkey);
        u32 mC = __match_any_sync(0xFFFFFFFFu, ckey);
        u32 earlier = (1u << lane) - 1u;
        bool conf = (((mR | mC) & earlier) != 0u);
        u32 cm = __ballot_sync(0xFFFFFFFFu, conf);
        if (lane == 0) sConfB[w] = cm;
    }
    __syncthreads();

    // ================= PHASE B: warp 0, compacted keys =================
    if (wid == 0) {
        int assigned = scan_staged(sFlat, m2, sConfB, lane, rowUsedB, colUsed, colOf, scnt_s);

        // ---- legacy gmem tail (only if staged prefix exhausted) ----
        for (int base = STAGE_KEYS; base < (int)total && assigned < NROWS; base += 32) {
            int i = base + lane;
            u64 key = (i < (int)total) ? __ldg(&g_keys[i]) : 0ull;
            u32 flat = 0xFFFFFFu - (u32)(key & 0xFFFFFFu);
            int r = (int)((flat >> 14) & 1023u);
            int c = (int)(flat & 0x3FFFu);
            bool isv = (key != 0ull);
            bool valid = isv && !rowUsedB[r] && !bit_test(colUsed, c);
            u32 vm = __ballot_sync(0xFFFFFFFFu, valid);
            u32 rkey = isv ? (u32)r : (u32)(NROWS + lane);
            u32 ckey = isv ? (u32)c : (u32)(NCOLS + lane);
            u32 mR = __match_any_sync(0xFFFFFFFFu, rkey);
            u32 mC = __match_any_sync(0xFFFFFFFFu, ckey);
            u32 myConf = (mR | mC) & ((1u << lane) - 1u);
            u32 conf = __ballot_sync(0xFFFFFFFFu, myConf != 0u);
            u32 acc = vm & ~conf;
            u32 quest = vm & conf;
            while (quest) {
                int q = __ffs(quest) - 1; quest &= quest - 1u;
                u32 em = __shfl_sync(0xFFFFFFFFu, myConf, q);
                if ((em & acc) == 0u) acc |= (1u << q);
            }
            if ((acc >> lane) & 1u) {
                rowUsedB[r] = 1;
                atomicOr(&colUsed[c >> 5], 1u << (c & 31));
                colOf[r] = (unsigned short)c;
            }
            assigned += __popc(acc);
            __syncwarp();
        }
        if (lane == 0) scnt_s = assigned;
    }

    // ---- exact fallback: masked global argmax for any unassigned rows ----
    while (true) {
        __syncthreads();
        if (scnt_s >= NROWS) break;
        u64 best = 0;
        for (int i = tid; i < NTOT; i += 1024) {
            int r = i >> 14;
            if (rowUsedB[r]) continue;
            int c = i & 0x3FFF;
            if (bit_test(colUsed, c)) continue;
            float v = cost[i];
            u32 u = __float_as_uint(v);
            u32 enc = (u & 0x80000000u) ? ~u : (u | 0x80000000u);
            u64 kk = ((u64)enc << 24) | (u64)(0xFFFFFFu - (u32)i);
            if (kk > best) best = kk;
        }
        #pragma unroll
        for (int o = 16; o > 0; o >>= 1) {
            u64 t2 = __shfl_down_sync(0xFFFFFFFFu, best, o);
            if (t2 > best) best = t2;
        }
        if (lane == 0) redBuf[wid] = best;
        __syncthreads();
        if (tid < 32) {
            u64 b = redBuf[tid];
            #pragma unroll
            for (int o = 16; o > 0; o >>= 1) {
                u64 t2 = __shfl_down_sync(0xFFFFFFFFu, b, o);
                if (t2 > b) b = t2;
            }
            if (tid == 0) {
                int flat = 0xFFFFFF - (int)(b & 0xFFFFFFu);
                int r = flat >> 14, c = flat & 0x3FFF;
                rowUsedB[r] = 1;
                colUsed[c >> 5] |= 1u << (c & 31);
                colOf[r] = (unsigned short)c;
                scnt_s = scnt_s + 1;
            }
        }
        __syncthreads();
    }

    // ---- write output as float32: rows (arange) then cols ----
    if (out_size >= 2 * NROWS) {
        for (int i = tid; i < NROWS; i += 1024) {
            out[i] = (float)i;
            out[NROWS + i] = (float)colOf[i];
        }
    } else {
        for (int i = tid; i < NROWS && i < out_size; i += 1024)
            out[i] = (float)colOf[i];
    }

    // ---- self-clean for next call ----
    if (tid == 0) { g_total = 0; g_overflow = 0; }
}

extern "C" void kernel_launch(void* const* d_in, const int* in_sizes, int n_in,
                              void* d_out, int out_size) {
    const float* cost = (const float*)d_in[0];
    float* out = (float*)d_out;
    (void)in_sizes; (void)n_in;

    k_scatter<<<SC_GRID, SC_BLK>>>((const float4*)cost);
    k_scan<<<1, 1024>>>();
    k_sortbins<<<FBINS / SB_WARPS, SB_WARPS * 32>>>();
    k_final<<<1, 1024>>>(cost, out, out_size);
}

// round 15
// speedup vs baseline: 1.1191x; 1.1191x over previous
#include <cuda_runtime.h>
#include <cstdint>

typedef unsigned long long u64;
typedef unsigned int u32;

#define NROWS 1024
#define NCOLS 16384
#define NTOT (NROWS*NCOLS)
#define CAP 32768
#define FBINS 4096
#define HLO 2.0f
#define HSCALE 1024.0f
#define BIN_MIN 1060      // value threshold ~= 3.035
#define BCAP 128

#define SC_GRID 4096
#define SC_BLK 256
#define SC_STRIDE (SC_GRID*SC_BLK)   // NTOT/4 = 4*SC_STRIDE exactly

#define STAGE_KEYS 10240
#define PHA_KEYS 2048
#define PHA_WINS (PHA_KEYS/32)          // 64
#define COMP_CHUNKS ((STAGE_KEYS-PHA_KEYS)/1024)  // 8
#define MAXB_WINS ((STAGE_KEYS-PHA_KEYS+31)/32)   // 256
#define FLAT_INVALID 0xFFFFFFFFu

#define SB_WARPS 8

// device-global scratch (no allocations allowed)
// Self-cleaning invariant: at kernel_launch entry, g_bincnt[]==0 and
// g_total==g_overflow==0 (zero-init at load; re-established every call).
__device__ u32 g_bincnt[FBINS];
__device__ u32 g_binoff[FBINS];
__device__ u32 g_total;
__device__ u32 g_overflow;
__device__ u64 g_bucket[FBINS * BCAP];   // 4 MB
__device__ u64 g_keys[CAP];

__device__ __forceinline__ int binof(float v) {
    int b = (int)((v - HLO) * HSCALE);
    return (b > FBINS - 1) ? (FBINS - 1) : b;
}

// ONE full-matrix pass: scatter candidates (binof(v) >= BIN_MIN) into buckets.
// Fast path: signed-int compare == float compare for non-NaN (negatives map
// to negative ints), so max(int lanes) >= bits(3.0f) filters whole vectors
// with 3 IMNMX + 1 ISETP. NaNs passing coarse test fail the exact float
// test inside -> candidate set identical.
__global__ void __launch_bounds__(SC_BLK)
k_scatter(const float4* __restrict__ c4) {
    const int THR = 0x40400000;   // bits of 3.0f
    int idx = blockIdx.x * SC_BLK + threadIdx.x;
    int4 vv[4];
    #pragma unroll
    for (int k = 0; k < 4; k++) vv[k] = ((const int4*)c4)[idx + k * SC_STRIDE];   // MLP=4
    #pragma unroll
    for (int k = 0; k < 4; k++) {
        int mx = max(max(vv[k].x, vv[k].y), max(vv[k].z, vv[k].w));
        if (mx >= THR) {
            int i = idx + k * SC_STRIDE;
            int w[4] = { vv[k].x, vv[k].y, vv[k].z, vv[k].w };
            #pragma unroll
            for (int q = 0; q < 4; q++) {
                float a = __int_as_float(w[q]);
                if (a >= 3.0f) {
                    int b = binof(a);
                    if (b >= BIN_MIN) {
                        u32 pos = atomicAdd(&g_bincnt[b], 1u);
                        if (pos < BCAP) {
                            u32 flat = (u32)(i * 4 + q);
                            u32 enc = (u32)w[q];   // candidates > 0: bits order-preserving
                            g_bucket[b * BCAP + pos] = ((u64)enc << 24) | (u64)(0xFFFFFFu - flat);
                        } else {
                            g_overflow = 1;
                        }
                    }
                }
            }
        }
    }
}

// one block: suffix-sum bucket counts (descending bins) via shuffle scan
__global__ void __launch_bounds__(1024)
k_scan() {
    __shared__ u32 warpsum[32];
    int tid = threadIdx.x;
    int lane = tid & 31, w = tid >> 5;

    u32 x[4], pre[4];
    u32 run = 0;
    #pragma unroll
    for (int q = 0; q < 4; q++) {
        int b = FBINS - 1 - (tid * 4 + q);
        x[q] = g_bincnt[b];
        pre[q] = run;
        run += x[q];
    }
    u32 v = run;
    #pragma unroll
    for (int o = 1; o < 32; o <<= 1) {
        u32 t = __shfl_up_sync(0xFFFFFFFFu, v, o);
        if (lane >= o) v += t;
    }
    if (lane == 31) warpsum[w] = v;
    __syncthreads();
    if (w == 0) {
        u32 s = warpsum[lane];
        #pragma unroll
        for (int o = 1; o < 32; o <<= 1) {
            u32 t = __shfl_up_sync(0xFFFFFFFFu, s, o);
            if (lane >= o) s += t;
        }
        warpsum[lane] = s;
    }
    __syncthreads();
    u32 excl = v - run + ((w > 0) ? warpsum[w - 1] : 0u);

    #pragma unroll
    for (int q = 0; q < 4; q++) {
        int b = FBINS - 1 - (tid * 4 + q);
        u32 S = excl + pre[q] + x[q];
        g_binoff[b] = S - x[q];
    }
    if (tid == 0) {
        u32 total = warpsum[31];
        if (total > CAP) { g_overflow = 1; total = 0; }
        g_total = total;
    }
}

// warp-per-bin: sort bucket desc (<=128 elems) into g_keys; self-clean bincnt
__global__ void __launch_bounds__(SB_WARPS * 32)
k_sortbins() {
    __shared__ u64 sk[SB_WARPS][BCAP];
    int w = threadIdx.x >> 5, lane = threadIdx.x & 31;
    int b = blockIdx.x * SB_WARPS + w;
    u32 cnt = g_bincnt[b];
    if (lane == 0) g_bincnt[b] = 0;          // self-clean for next call
    if (cnt == 0) return;
    if (cnt > BCAP) cnt = BCAP;              // overflow already flagged; data unused
    u32 off = g_binoff[b];
    if (cnt == 1) { if (lane == 0) g_keys[off] = g_bucket[b * BCAP]; return; }

    u32 m = 2; while (m < cnt) m <<= 1;      // m <= 128
    for (u32 i = lane; i < m; i += 32) sk[w][i] = (i < cnt) ? g_bucket[b * BCAP + i] : 0ull;
    __syncwarp();
    for (u32 k = 2; k <= m; k <<= 1) {
        for (u32 j = k >> 1; j > 0; j >>= 1) {
            for (u32 i = lane; i < m; i += 32) {
                u32 p = i ^ j;
                if (p > i) {
                    u64 a = sk[w][i], bb = sk[w][p];
                    bool desc = ((i & k) == 0);
                    if (desc ? (a < bb) : (a > bb)) { sk[w][i] = bb; sk[w][p] = a; }
                }
            }
            __syncwarp();
        }
    }
    for (u32 i = lane; i < cnt; i += 32) g_keys[off + i] = sk[w][i];
}

__device__ __forceinline__ bool bit_test(const u32* bits, int i) {
    return (bits[i >> 5] >> (i & 31)) & 1u;
}

// greedy scan over globally-descending keys + exact fallback + output
// (structure identical to the 53.8us R12 kernel: phase A over 2048 keys,
//  one mid-scan compaction, phase B; quest via precomputed masks + shared
//  bit_tests — match_any stays OUT of warp 0's critical path)
__global__ void __launch_bounds__(1024, 1)
k_final(const float* __restrict__ cost, float* __restrict__ out, int out_size) {
    __shared__ u32 sFlat[STAGE_KEYS];          // 40960 B
    __shared__ u32 sConfA[PHA_WINS];           // 256 B
    __shared__ u32 sConfB[MAXB_WINS];          // 1024 B
    __shared__ unsigned char rowUsedB[NROWS];  // 1024 B
    __shared__ u32 colUsed[NCOLS / 32];        // 2048 B
    __shared__ unsigned short colOf[NROWS];    // 2048 B
    __shared__ u32 warpS[32];
    __shared__ u64 redBuf[32];
    __shared__ int scnt_s, m2_s;

    int tid = threadIdx.x;
    int lane = tid & 31;
    int wid = tid >> 5;
    u32 total = g_total;
    if (g_overflow) total = 0;   // pathological: pure-fallback path (exact)

    for (int i = tid; i < NCOLS / 32; i += 1024) colUsed[i] = 0;
    for (int i = tid; i < NROWS; i += 1024) { rowUsedB[i] = 0; colOf[i] = 0; }
    if (tid == 0) { scnt_s = 0; m2_s = 0; }

    // ---- stage first STAGE_KEYS flats into shared (all warps) ----
    for (int i = tid; i < STAGE_KEYS; i += 1024)
        sFlat[i] = (i < (int)total) ? (0xFFFFFFu - (u32)(g_keys[i] & 0xFFFFFFu))
                                    : FLAT_INVALID;
    __syncthreads();

    // ---- precompute phase-A conflict masks (warps in parallel) ----
    for (int w = wid; w < PHA_WINS; w += 32) {
        u32 flat = sFlat[w * 32 + lane];
        bool v = (flat != FLAT_INVALID);
        u32 rkey = v ? ((flat >> 14) & 1023u) : (u32)(NROWS + lane);
        u32 ckey = v ? (flat & 0x3FFFu) : (u32)(NCOLS + lane);
        u32 mR = __match_any_sync(0xFFFFFFFFu, rkey);
        u32 mC = __match_any_sync(0xFFFFFFFFu, ckey);
        u32 earlier = (1u << lane) - 1u;
        bool conf = (((mR | mC) & earlier) != 0u);
        u32 cm = __ballot_sync(0xFFFFFFFFu, conf);
        if (lane == 0) sConfA[w] = cm;
    }
    __syncthreads();

    // ================= PHASE A: warp 0, first PHA_KEYS keys =================
    if (wid == 0) {
        int assigned = 0;
        int lim = ((int)total < PHA_KEYS) ? (int)total : PHA_KEYS;
        u32 flat = (0 < lim) ? sFlat[lane] : FLAT_INVALID;
        for (int base = 0; base < lim && assigned < NROWS; base += 32) {
            u32 nflat = (base + 32 < PHA_KEYS) ? sFlat[base + 32 + lane] : FLAT_INVALID;
            u32 conf = sConfA[base >> 5];
            int r = (int)((flat >> 14) & 1023u);
            int c = (int)(flat & 0x3FFFu);
            unsigned char rb = rowUsedB[r];
            u32 cw = colUsed[c >> 5];
            bool valid = (flat != FLAT_INVALID) && !rb && !((cw >> (c & 31)) & 1u);
            u32 validmask = __ballot_sync(0xFFFFFFFFu, valid);
            u32 accmask = validmask & ~conf;
            if ((accmask >> lane) & 1u) {
                rowUsedB[r] = 1;
                atomicOr(&colUsed[c >> 5], 1u << (c & 31));
                colOf[r] = (unsigned short)c;
            }
            assigned += __popc(accmask);

            u32 quest = validmask & conf;
            if (quest) {
                __syncwarp();
                while (quest) {
                    int q = __ffs(quest) - 1;
                    quest &= quest - 1u;
                    int qr = __shfl_sync(0xFFFFFFFFu, r, q);
                    int qc = __shfl_sync(0xFFFFFFFFu, c, q);
                    bool ok = !rowUsedB[qr] && !bit_test(colUsed, qc);
                    if (ok) {
                        if (lane == 0) {
                            rowUsedB[qr] = 1;
                            atomicOr(&colUsed[qc >> 5], 1u << (qc & 31));
                            colOf[qr] = (unsigned short)qc;
                        }
                        assigned++;
                        __syncwarp();
                    }
                }
            }
            __syncwarp();
            flat = nflat;
        }
        if (lane == 0) scnt_s = assigned;
    }
    __syncthreads();

    // ====== MID-SCAN COMPACTION (all threads; order-preserving) ======
    {
        int m2base = 0;
        for (int k = 0; k < COMP_CHUNKS; k++) {
            int idx = PHA_KEYS + k * 1024 + tid;
            u32 f = sFlat[idx];
            bool keep = (f != FLAT_INVALID) && !rowUsedB[(f >> 14) & 1023u]
                        && !bit_test(colUsed, f & 0x3FFF);
            u32 ball = __ballot_sync(0xFFFFFFFFu, keep);
            int myoff = __popc(ball & ((1u << lane) - 1u));
            if (lane == 0) warpS[wid] = (u32)__popc(ball);
            __syncthreads();
            if (tid < 32) {
                u32 v = warpS[tid];
                #pragma unroll
                for (int o = 1; o < 32; o <<= 1) {
                    u32 t2 = __shfl_up_sync(0xFFFFFFFFu, v, o);
                    if (tid >= o) v += t2;
                }
                warpS[tid] = v;
            }
            __syncthreads();
            int wexcl = (wid > 0) ? (int)warpS[wid - 1] : 0;
            int chunkTot = (int)warpS[31];
            if (keep) sFlat[m2base + wexcl + myoff] = f;
            m2base += chunkTot;
            __syncthreads();
        }
        if (tid == 0) m2_s = m2base;
    }
    __syncthreads();

    // ---- precompute phase-B conflict masks over compacted list ----
    int m2 = m2_s;
    int nwinB = (m2 + 31) >> 5;
    for (int w = wid; w < nwinB; w += 32) {
        int i = w * 32 + lane;
        u32 flat = (i < m2) ? sFlat[i] : FLAT_INVALID;
        bool v = (flat != FLAT_INVALID);
        u32 rkey = v ? ((flat >> 14) & 1023u) : (u32)(NROWS + lane);
        u32 ckey = v ? (flat & 0x3FFFu) : (u32)(NCOLS + lane);
        u32 mR = __match_any_sync(0xFFFFFFFFu, rkey);
        u32 mC = __match_any_sync(0xFFFFFFFFu, ckey);
        u32 earlier = (1u << lane) - 1u;
        bool conf = (((mR | mC) & earlier) != 0u);
        u32 cm = __ballot_sync(0xFFFFFFFFu, conf);
        if (lane == 0) sConfB[w] = cm;
    }
    __syncthreads();

    // ================= PHASE B: warp 0, compacted keys =================
    if (wid == 0) {
        int assigned = scnt_s;
        u32 flat = (0 < m2 && lane < m2) ? sFlat[lane] : FLAT_INVALID;
        for (int base = 0; base < m2 && assigned < NROWS; base += 32) {
            int ni = base + 32 + lane;
            u32 nflat = (ni < m2) ? sFlat[ni] : FLAT_INVALID;
            u32 conf = sConfB[base >> 5];
            int r = (int)((flat >> 14) & 1023u);
            int c = (int)(flat & 0x3FFFu);
            unsigned char rb = (flat != FLAT_INVALID) ? rowUsedB[r] : (unsigned char)1;
            u32 cw = colUsed[c >> 5];
            bool valid = (flat != FLAT_INVALID) && !rb && !((cw >> (c & 31)) & 1u);
            u32 validmask = __ballot_sync(0xFFFFFFFFu, valid);
            u32 accmask = validmask & ~conf;
            if ((accmask >> lane) & 1u) {
                rowUsedB[r] = 1;
                atomicOr(&colUsed[c >> 5], 1u << (c & 31));
                colOf[r] = (unsigned short)c;
            }
            assigned += __popc(accmask);

            u32 quest = validmask & conf;
            if (quest) {
                __syncwarp();
                while (quest) {
                    int q = __ffs(quest) - 1;
                    quest &= quest - 1u;
                    int qr = __shfl_sync(0xFFFFFFFFu, r, q);
                    int qc = __shfl_sync(0xFFFFFFFFu, c, q);
                    bool ok = !rowUsedB[qr] && !bit_test(colUsed, qc);
                    if (ok) {
                        if (lane == 0) {
                            rowUsedB[qr] = 1;
                            atomicOr(&colUsed[qc >> 5], 1u << (qc & 31));
                            colOf[qr] = (unsigned short)qc;
                        }
                        assigned++;
                        __syncwarp();
                    }
                }
            }
            __syncwarp();
            flat = nflat;
        }
        // ---- legacy gmem tail (only if staged prefix exhausted) ----
        for (int base = STAGE_KEYS; base < (int)total && assigned < NROWS; base += 32) {
            int i = base + lane;
            u64 key = (i < (int)total) ? __ldg(&g_keys[i]) : 0ull;
            u32 flat2 = 0xFFFFFFu - (u32)(key & 0xFFFFFFu);
            int r = (int)((flat2 >> 14) & 1023u);
            int c = (int)(flat2 & 0x3FFFu);
            bool isv = (key != 0ull);
            bool valid = isv && !rowUsedB[r] && !bit_test(colUsed, c);
            u32 validmask = __ballot_sync(0xFFFFFFFFu, valid);
            u32 rkey = isv ? (u32)r : (u32)(NROWS + lane);
            u32 ckey = isv ? (u32)c : (u32)(NCOLS + lane);
            u32 mR = __match_any_sync(0xFFFFFFFFu, rkey);
            u32 mC = __match_any_sync(0xFFFFFFFFu, ckey);
            u32 earlier = (1u << lane) - 1u;
            bool conflictE = (((mR | mC) & earlier & validmask) != 0u);
            bool acc0 = valid && !conflictE;
            u32 accmask = __ballot_sync(0xFFFFFFFFu, acc0);
            if (acc0) {
                rowUsedB[r] = 1;
                atomicOr(&colUsed[c >> 5], 1u << (c & 31));
                colOf[r] = (unsigned short)c;
            }
            assigned += __popc(accmask);
            __syncwarp();
            u32 quest = __ballot_sync(0xFFFFFFFFu, valid && conflictE);
            while (quest) {
                int q = __ffs(quest) - 1;
                quest &= quest - 1u;
                int qr = __shfl_sync(0xFFFFFFFFu, r, q);
                int qc = __shfl_sync(0xFFFFFFFFu, c, q);
                bool ok = !rowUsedB[qr] && !bit_test(colUsed, qc);
                if (ok) {
                    if (lane == 0) {
                        rowUsedB[qr] = 1;
                        atomicOr(&colUsed[qc >> 5], 1u << (qc & 31));
                        colOf[qr] = (unsigned short)qc;
                    }
                    assigned++;
                    __syncwarp();
                }
            }
        }
        if (lane == 0) scnt_s = assigned;
    }

    // ---- exact fallback: masked global argmax for any unassigned rows ----
    while (true) {
        __syncthreads();
        if (scnt_s >= NROWS) break;
        u64 best = 0;
        for (int i = tid; i < NTOT; i += 1024) {
            int r = i >> 14;
            if (rowUsedB[r]) continue;
            int c = i & 0x3FFF;
            if (bit_test(colUsed, c)) continue;
            float v = cost[i];
            u32 u = __float_as_uint(v);
            u32 enc = (u & 0x80000000u) ? ~u : (u | 0x80000000u);
            u64 kk = ((u64)enc << 24) | (u64)(0xFFFFFFu - (u32)i);
            if (kk > best) best = kk;
        }
        #pragma unroll
        for (int o = 16; o > 0; o >>= 1) {
            u64 t2 = __shfl_down_sync(0xFFFFFFFFu, best, o);
            if (t2 > best) best = t2;
        }
        if (lane == 0) redBuf[wid] = best;
        __syncthreads();
        if (tid < 32) {
            u64 b = redBuf[tid];
            #pragma unroll
            for (int o = 16; o > 0; o >>= 1) {
                u64 t2 = __shfl_down_sync(0xFFFFFFFFu, b, o);
                if (t2 > b) b = t2;
            }
            if (tid == 0) {
                int flat = 0xFFFFFF - (int)(b & 0xFFFFFFu);
                int r = flat >> 14, c = flat & 0x3FFF;
                rowUsedB[r] = 1;
                colUsed[c >> 5] |= 1u << (c & 31);
                colOf[r] = (unsigned short)c;
                scnt_s = scnt_s + 1;
            }
        }
        __syncthreads();
    }

    // ---- write output as float32: rows (arange) then cols ----
    if (out_size >= 2 * NROWS) {
        for (int i = tid; i < NROWS; i += 1024) {
            out[i] = (float)i;
            out[NROWS + i] = (float)colOf[i];
        }
    } else {
        for (int i = tid; i < NROWS && i < out_size; i += 1024)
            out[i] = (float)colOf[i];
    }

    // ---- self-clean for next call ----
    if (tid == 0) { g_total = 0; g_overflow = 0; }
}

extern "C" void kernel_launch(void* const* d_in, const int* in_sizes, int n_in,
                              void* d_out, int out_size) {
    const float* cost = (const float*)d_in[0];
    float* out = (float*)d_out;
    (void)in_sizes; (void)n_in;

    k_scatter<<<SC_GRID, SC_BLK>>>((const float4*)cost);
    k_scan<<<1, 1024>>>();
    k_sortbins<<<FBINS / SB_WARPS, SB_WARPS * 32>>>();
    k_final<<<1, 1024>>>(cost, out, out_size);
}